// round 9
// baseline (speedup 1.0000x reference)
#include <cuda_runtime.h>
#include <cstdint>

// B=128, N=16384, T=64. Warp-private 576-elem register window: 4 fully-owned
// slots (512 elems -> 4 dense coalesced STG.128/step) + 1 split halo slot
// (lanes 0-15: left 64-elem halo, lanes 16-31: right 64-elem halo; >= T-1=63).
// 4096 warps total = single fully-resident wave at unconstrained regs.
// No barriers, no smem, packed f32x2 math, batched shuffles.
constexpr int N_ELEM   = 16384;
constexpr int NTHREADS = 128;   // 4 warps per CTA
constexpr int OWNED    = 512;
constexpr int NO       = 4;     // owned float4 slots per thread

__device__ __forceinline__ uint64_t pack2(float lo, float hi) {
    uint64_t o; asm("mov.b64 %0, {%1, %2};" : "=l"(o) : "f"(lo), "f"(hi)); return o;
}
__device__ __forceinline__ void unpack2(float& lo, float& hi, uint64_t in) {
    asm("mov.b64 {%0, %1}, %2;" : "=f"(lo), "=f"(hi) : "l"(in));
}
__device__ __forceinline__ uint64_t add2(uint64_t a, uint64_t b) {
    uint64_t r; asm("add.rn.f32x2 %0, %1, %2;" : "=l"(r) : "l"(a), "l"(b)); return r;
}
__device__ __forceinline__ uint64_t fma2(uint64_t a, uint64_t b, uint64_t c) {
    uint64_t r; asm("fma.rn.f32x2 %0, %1, %2, %3;" : "=l"(r) : "l"(a), "l"(b), "l"(c)); return r;
}

// In-place heat update of one float4 given scalar neighbors.
__device__ __forceinline__ void step4(float4& v, float up, float dn,
                                      uint64_t A2, uint64_t M2)
{
    const uint64_t pP0 = pack2(v.x, v.y);
    const uint64_t pP1 = pack2(v.z, v.w);
    const uint64_t pUA = pack2(up,  v.x);
    const uint64_t pBC = pack2(v.y, v.z);
    const uint64_t pDN = pack2(v.w, dn);
    uint64_t s0 = add2(pUA, pBC);           // (up+y, x+z)
    uint64_t s1 = add2(pBC, pDN);           // (y+w, z+dn)
    s0 = fma2(M2, pP0, s0);                 // laplacian pairs
    s1 = fma2(M2, pP1, s1);
    const uint64_t r0 = fma2(A2, s0, pP0);  // x + alpha*lap
    const uint64_t r1 = fma2(A2, s1, pP1);
    unpack2(v.x, v.y, r0);
    unpack2(v.z, v.w, r1);
}

__global__ __launch_bounds__(NTHREADS)
void heat1d_warp_kernel(const float* __restrict__ f0,
                        const float* __restrict__ log_alpha,
                        float* __restrict__ out, int T)
{
    const int tid = threadIdx.x;
    const int l   = tid & 31;
    const int gw  = blockIdx.x * (NTHREADS / 32) + (tid >> 5);
    const int wpr = N_ELEM / OWNED;       // 32 warps per row
    const int b   = gw / wpr;
    const int w   = gw % wpr;

    float alpha = expf(*log_alpha);
    alpha = fminf(fmaxf(alpha, 0.001f), 1.0f);
    const uint64_t A2 = pack2(alpha, alpha);
    const uint64_t M2 = pack2(-2.0f, -2.0f);

    const int wstart = w * OWNED;
    const float* row = f0 + (size_t)b * N_ELEM;
    const float4* inv4 = reinterpret_cast<const float4*>(row);
    float4* outw = reinterpret_cast<float4*>(out + (size_t)b * T * N_ELEM)
                   + (wstart >> 2);

    // Owned slots: Ok lane l = elements [wstart + 128k + 4l, +4).
    float4 O[NO];
#pragma unroll
    for (int k = 0; k < NO; k++) O[k] = inv4[(wstart >> 2) + 32 * k + l];

    // Halo slot: lanes 0-15 left halo [wstart-64, wstart),
    //            lanes 16-31 right halo [wstart+512, wstart+576).
    float4 H;
    {
        const int he = (l < 16) ? (wstart - 64 + 4 * l)
                                : (wstart + OWNED + 4 * (l - 16));
        if (he >= 0 && he <= N_ELEM - 4) {
            H = inv4[he >> 2];
        } else {  // only the two row-edge warps; values never feed owned data
            H.x = row[min(max(he + 0, 0), N_ELEM - 1)];
            H.y = row[min(max(he + 1, 0), N_ELEM - 1)];
            H.z = row[min(max(he + 2, 0), N_ELEM - 1)];
            H.w = row[min(max(he + 3, 0), N_ELEM - 1)];
        }
    }

    // Emit t = 0: four dense coalesced stores.
#pragma unroll
    for (int k = 0; k < NO; k++) __stcs(&outw[32 * k + l], O[k]);

    const bool atL = (w == 0);
    const bool atR = (w == wpr - 1);
    const int upsrc = (l + 31) & 31;
    const int dnsrc = (l + 1)  & 31;
    const int bxsrc = l ^ 15;   // routes all 4 cross-region boundary scalars

    float4* outt = outw;
    for (int t = 1; t < T; t++) {
        outt += N_ELEM / 4;

        // Boundary exchange (lane0<->15, lane16<->31):
        //  lane0  publishes O0.x      -> lane15 (halo-left's dn)
        //  lane15 publishes H.w       -> lane0  (O0's up)
        //  lane16 publishes H.x       -> lane31 (O3's dn)
        //  lane31 publishes O[NO-1].w -> lane16 (halo-right's up)
        const float bpay = (l == 0)  ? O[0].x :
                           (l == 15) ? H.w    :
                           (l == 16) ? H.x    : O[NO - 1].w;
        const float bx = __shfl_sync(0xffffffffu, bpay, bxsrc);

        // Batched rotated neighbor shuffles; payload-select handles the
        // O(k)<->O(k+1) crossings.
        float up[NO], dn[NO], upH, dnH;
#pragma unroll
        for (int k = 0; k < NO; k++) {
            float us = (l == 31 && k > 0)      ? O[k - 1].w : O[k].w;
            float ds = (l == 0  && k < NO - 1) ? O[k + 1].x : O[k].x;
            up[k] = __shfl_sync(0xffffffffu, us, upsrc);
            dn[k] = __shfl_sync(0xffffffffu, ds, dnsrc);
        }
        upH = __shfl_sync(0xffffffffu, H.w, upsrc);
        dnH = __shfl_sync(0xffffffffu, H.x, dnsrc);

        // Boundary fixups. atL/atR pin the true row edge (exact reference
        // edge padding); interior fake edges (halo outer ends) clamp —
        // staleness travels 1 elem/step, never reaching owned data in T-1=63.
        if (l == 0)  { up[0]      = atL ? O[0].x      : bx;  upH = H.x; }
        if (l == 31) { dn[NO - 1] = atR ? O[NO - 1].w : bx;  dnH = H.w; }
        if (l == 16)   upH = bx;
        if (l == 15)   dnH = bx;

#pragma unroll
        for (int k = 0; k < NO; k++) step4(O[k], up[k], dn[k], A2, M2);
        step4(H, upH, dnH, A2, M2);

#pragma unroll
        for (int k = 0; k < NO; k++) __stcs(&outt[32 * k + l], O[k]);
    }
}

extern "C" void kernel_launch(void* const* d_in, const int* in_sizes, int n_in,
                              void* d_out, int out_size)
{
    const float* f0        = (const float*)d_in[0];
    const float* log_alpha = (const float*)d_in[1];
    float*       out       = (float*)d_out;

    const int B = in_sizes[0] / N_ELEM;    // 128
    const int T = out_size / in_sizes[0];  // 64

    const int total_warps = B * (N_ELEM / OWNED);           // 4096
    const int n_blocks    = total_warps / (NTHREADS / 32);  // 1024

    heat1d_warp_kernel<<<n_blocks, NTHREADS>>>(f0, log_alpha, out, T);
}

// round 10
// speedup vs baseline: 1.1020x; 1.1020x over previous
#include <cuda_runtime.h>
#include <cstdint>

// B=128, N=16384, T=64. Warp-private 384-elem register window: 2 fully-owned
// slots (256 elems, dense coalesced STG.128) + 1 split halo slot (lanes 0-15:
// left 64-elem halo, lanes 16-31: right 64-elem halo; >= T-1=63).
// Software-pipelined: iteration s STORES state s (computed last iteration),
// then computes state s+1 -> stores issue with zero data-dependency wait.
// No barriers, no smem, packed f32x2 math, batched shuffles.
constexpr int N_ELEM   = 16384;
constexpr int NTHREADS = 128;   // 4 warps per CTA
constexpr int OWNED    = 256;

__device__ __forceinline__ uint64_t pack2(float lo, float hi) {
    uint64_t o; asm("mov.b64 %0, {%1, %2};" : "=l"(o) : "f"(lo), "f"(hi)); return o;
}
__device__ __forceinline__ void unpack2(float& lo, float& hi, uint64_t in) {
    asm("mov.b64 {%0, %1}, %2;" : "=f"(lo), "=f"(hi) : "l"(in));
}
__device__ __forceinline__ uint64_t add2(uint64_t a, uint64_t b) {
    uint64_t r; asm("add.rn.f32x2 %0, %1, %2;" : "=l"(r) : "l"(a), "l"(b)); return r;
}
__device__ __forceinline__ uint64_t fma2(uint64_t a, uint64_t b, uint64_t c) {
    uint64_t r; asm("fma.rn.f32x2 %0, %1, %2, %3;" : "=l"(r) : "l"(a), "l"(b), "l"(c)); return r;
}

// In-place heat update of one float4 given scalar neighbors.
__device__ __forceinline__ void step4(float4& v, float up, float dn,
                                      uint64_t A2, uint64_t M2)
{
    const uint64_t pP0 = pack2(v.x, v.y);
    const uint64_t pP1 = pack2(v.z, v.w);
    const uint64_t pUA = pack2(up,  v.x);
    const uint64_t pBC = pack2(v.y, v.z);
    const uint64_t pDN = pack2(v.w, dn);
    uint64_t s0 = add2(pUA, pBC);           // (up+y, x+z)
    uint64_t s1 = add2(pBC, pDN);           // (y+w, z+dn)
    s0 = fma2(M2, pP0, s0);                 // laplacian pairs
    s1 = fma2(M2, pP1, s1);
    const uint64_t r0 = fma2(A2, s0, pP0);  // x + alpha*lap
    const uint64_t r1 = fma2(A2, s1, pP1);
    unpack2(v.x, v.y, r0);
    unpack2(v.z, v.w, r1);
}

template <int TT>   // TT > 0: compile-time step count; TT == 0: runtime Trt
__global__ __launch_bounds__(NTHREADS)
void heat1d_warp_kernel(const float* __restrict__ f0,
                        const float* __restrict__ log_alpha,
                        float* __restrict__ out, int Trt)
{
    const int T = (TT > 0) ? TT : Trt;

    const int tid = threadIdx.x;
    const int l   = tid & 31;
    const int gw  = blockIdx.x * (NTHREADS / 32) + (tid >> 5);
    const int wpr = N_ELEM / OWNED;       // 64 warps per row
    const int b   = gw / wpr;
    const int w   = gw % wpr;

    float alpha = expf(*log_alpha);
    alpha = fminf(fmaxf(alpha, 0.001f), 1.0f);
    const uint64_t A2 = pack2(alpha, alpha);
    const uint64_t M2 = pack2(-2.0f, -2.0f);

    const int wstart = w * OWNED;
    const float* row = f0 + (size_t)b * N_ELEM;
    const float4* inv4 = reinterpret_cast<const float4*>(row);
    float4* outw = reinterpret_cast<float4*>(out + (size_t)b * T * N_ELEM)
                   + (wstart >> 2);

    // Owned slots: O0 lane l = elements [wstart+4l, +4); O1 = +128.
    float4 O0 = inv4[(wstart >> 2) + l];
    float4 O1 = inv4[(wstart >> 2) + 32 + l];
    // Halo slot: lanes 0-15 left halo [wstart-64, wstart),
    //            lanes 16-31 right halo [wstart+256, wstart+320).
    float4 H;
    {
        const int he = (l < 16) ? (wstart - 64 + 4 * l)
                                : (wstart + OWNED + 4 * (l - 16));
        if (he >= 0 && he <= N_ELEM - 4) {
            H = inv4[he >> 2];
        } else {  // only the two row-edge warps; values never feed owned data
            H.x = row[min(max(he + 0, 0), N_ELEM - 1)];
            H.y = row[min(max(he + 1, 0), N_ELEM - 1)];
            H.z = row[min(max(he + 2, 0), N_ELEM - 1)];
            H.w = row[min(max(he + 3, 0), N_ELEM - 1)];
        }
    }

    const bool atL = (w == 0);
    const bool atR = (w == wpr - 1);
    const int upsrc = (l + 31) & 31;
    const int dnsrc = (l + 1)  & 31;
    const int bxsrc = l ^ 15;   // routes all 4 cross-region boundary scalars

    float4* outt = outw;
#pragma unroll 3
    for (int s = 0; s < T - 1; s++) {
        // Store state s: data computed an entire iteration ago -> STG issues
        // immediately, overlapping the shuffles/math below.
        __stcs(&outt[l],      O0);
        __stcs(&outt[32 + l], O1);
        outt += N_ELEM / 4;

        // Boundary exchange (lane0<->15, lane16<->31):
        //  lane0  publishes O0.x -> lane15 (halo-left's dn)
        //  lane15 publishes H.w  -> lane0  (O0's up)
        //  lane16 publishes H.x  -> lane31 (O1's dn)
        //  lane31 publishes O1.w -> lane16 (halo-right's up)
        const float bpay = (l == 0)  ? O0.x :
                           (l == 15) ? H.w  :
                           (l == 16) ? H.x  : O1.w;
        const float bx = __shfl_sync(0xffffffffu, bpay, bxsrc);

        // Batched rotated neighbor shuffles; payload-select handles the
        // O0<->O1 crossings.
        float upO0 = __shfl_sync(0xffffffffu, O0.w, upsrc);
        float dnO0 = __shfl_sync(0xffffffffu, (l == 0)  ? O1.x : O0.x, dnsrc);
        float upO1 = __shfl_sync(0xffffffffu, (l == 31) ? O0.w : O1.w, upsrc);
        float dnO1 = __shfl_sync(0xffffffffu, O1.x, dnsrc);
        float upH  = __shfl_sync(0xffffffffu, H.w,  upsrc);
        float dnH  = __shfl_sync(0xffffffffu, H.x,  dnsrc);

        // Boundary fixups. atL/atR pin the true row edge (exact reference
        // edge padding); interior fake edges (halo outer ends) clamp —
        // staleness travels 1 elem/step, never reaching owned data in 63 steps.
        if (l == 0)  { upO0 = atL ? O0.x : bx;  upH = H.x; }
        if (l == 31) { dnO1 = atR ? O1.w : bx;  dnH = H.w; }
        if (l == 16)   upH = bx;
        if (l == 15)   dnH = bx;

        step4(O0, upO0, dnO0, A2, M2);
        step4(O1, upO1, dnO1, A2, M2);
        step4(H,  upH,  dnH,  A2, M2);
    }

    // Final state T-1.
    __stcs(&outt[l],      O0);
    __stcs(&outt[32 + l], O1);
}

extern "C" void kernel_launch(void* const* d_in, const int* in_sizes, int n_in,
                              void* d_out, int out_size)
{
    const float* f0        = (const float*)d_in[0];
    const float* log_alpha = (const float*)d_in[1];
    float*       out       = (float*)d_out;

    const int B = in_sizes[0] / N_ELEM;    // 128
    const int T = out_size / in_sizes[0];  // 64

    const int total_warps = B * (N_ELEM / OWNED);           // 8192
    const int n_blocks    = total_warps / (NTHREADS / 32);  // 2048

    if (T == 64) {
        heat1d_warp_kernel<64><<<n_blocks, NTHREADS>>>(f0, log_alpha, out, T);
    } else {
        heat1d_warp_kernel<0><<<n_blocks, NTHREADS>>>(f0, log_alpha, out, T);
    }
}